// round 5
// baseline (speedup 1.0000x reference)
#include <cuda_runtime.h>

// ---------------------------------------------------------------------------
// Drifter: x_{n+1} = x_n + drift(x_n)*20, 100 steps, T=101 samples stored.
// drift(x) = sum_f sw[f]*sin(f x) + cw[f]*cos(f x)  = Re( P(e^{ix}) ),
// P(z) = sum_f (cw[f] - i*sw[f]) z^f  -> complex Horner, 7 iterations.
// Two batch elements per thread, packed into f32x2 (FFMA2) ops.
// Outputs: out[0 : B*T]   = t_mesh (row b = 0,20,...,2000)
//          out[B*T : 2BT] = xt wrapped to [-pi, pi)
// Stores staged in shared memory -> coalesced 128B warp stores.
// ---------------------------------------------------------------------------

typedef unsigned long long u64;

__device__ __forceinline__ u64 pk2(float lo, float hi) {
    u64 r; asm("mov.b64 %0, {%1, %2};" : "=l"(r) : "f"(lo), "f"(hi)); return r;
}
__device__ __forceinline__ float2 upk2(u64 v) {
    float2 f; asm("mov.b64 {%0, %1}, %2;" : "=f"(f.x), "=f"(f.y) : "l"(v)); return f;
}
__device__ __forceinline__ u64 fma2(u64 a, u64 b, u64 c) {
    u64 d; asm("fma.rn.f32x2 %0, %1, %2, %3;" : "=l"(d) : "l"(a), "l"(b), "l"(c)); return d;
}
__device__ __forceinline__ u64 mul2(u64 a, u64 b) {
    u64 d; asm("mul.rn.f32x2 %0, %1, %2;" : "=l"(d) : "l"(a), "l"(b)); return d;
}

#define FS      8
#define T_PTS   101
#define DT_F    20.0f
#define TPB     128
#define EPB     256   // elements per block (2 per thread)
#define CHUNK   32    // time-steps staged in smem per flush

__device__ __forceinline__ float wrapf(float x) {
    // (x + pi) mod 2pi - pi  ==  x - 2pi * floor(x/(2pi) + 0.5)
    float k = floorf(__fmaf_rn(x, 0.15915494309189535f, 0.5f));
    return __fmaf_rn(k, -6.283185307179586f, x);
}

__global__ void __launch_bounds__(TPB, 6)
drifter_kernel(const float* __restrict__ x0,
               const float* __restrict__ sw,
               const float* __restrict__ cw,
               float* __restrict__ out, int B)
{
    const int T = T_PTS;
    float* out_t = out;                       // t_mesh [B, T]
    float* out_x = out + (size_t)B * T;       // xt     [B, T]

    __shared__ float stage[EPB][CHUNK + 1];   // +1 pad: conflict-free

    const int tid  = threadIdx.x;
    const size_t base = (size_t)blockIdx.x * EPB;

    const size_t e0 = base + tid;
    const size_t e1 = base + TPB + tid;
    float xa = (e0 < (size_t)B) ? x0[e0] : 0.0f;
    float xb = (e1 < (size_t)B) ? x0[e1] : 0.0f;
    u64 x2 = pk2(xa, xb);

    // Packed (broadcast) coefficients: CWp[f] = cw[f], NSWp[f] = -sw[f]
    u64 CWp[FS], NSWp[FS];
#pragma unroll
    for (int f = 0; f < FS; ++f) {
        float c = __ldg(cw + f);
        float s = __ldg(sw + f);
        CWp[f]  = pk2(c, c);
        NSWp[f] = pk2(-s, -s);
    }
    const u64 NEG1 = pk2(-1.0f, -1.0f);
    const u64 DT2  = pk2(DT_F, DT_F);

    for (int chunk = 0; chunk < T; chunk += CHUNK) {
        const int clen = min(CHUNK, T - chunk);

        // ---- compute clen samples into the stage buffer ----
        for (int c = 0; c < clen; ++c) {
            float2 xv = upk2(x2);
            stage[tid][c]       = wrapf(xv.x);
            stage[tid + TPB][c] = wrapf(xv.y);

            // advance one Euler step (one extra harmless step after j=100)
            float sa, ca, sb, cb;
            __sincosf(xv.x, &sa, &ca);
            __sincosf(xv.y, &sb, &cb);
            u64 zr  = pk2(ca, cb);
            u64 zi  = pk2(sa, sb);
            u64 nzi = mul2(zi, NEG1);

            // complex Horner: acc = W7; acc = acc*z + Wf  (f = 6..1)
            u64 ar = CWp[FS - 1], ai = NSWp[FS - 1];
#pragma unroll
            for (int f = FS - 2; f >= 1; --f) {
                u64 tr = fma2(ai, nzi, CWp[f]);   // -ai*zi + cw_f
                u64 ti = fma2(ai, zr,  NSWp[f]);  //  ai*zr - sw_f
                u64 nr = fma2(ar, zr,  tr);
                ai     = fma2(ar, zi,  ti);
                ar     = nr;
            }
            // f = 0: only the real part is needed
            u64 tr    = fma2(ai, nzi, CWp[0]);
            u64 drift = fma2(ar, zr,  tr);
            x2 = fma2(drift, DT2, x2);            // x += drift * 20
        }

        __syncthreads();

        // ---- coalesced flush: warp w handles rows w, w+4, ... ----
        const int warp = tid >> 5;
        const int lane = tid & 31;
        if (lane < clen) {
            const float tval = DT_F * (float)(chunk + lane);
            float* px = out_x + (base + warp) * (size_t)T + chunk + lane;
            float* pt = out_t + (base + warp) * (size_t)T + chunk + lane;
#pragma unroll 4
            for (int r = warp; r < EPB; r += 4, px += 4 * T, pt += 4 * T) {
                if (base + (size_t)r < (size_t)B) {
                    *px = stage[r][lane];
                    *pt = tval;
                }
            }
        }
        __syncthreads();
    }
}

extern "C" void kernel_launch(void* const* d_in, const int* in_sizes, int n_in,
                              void* d_out, int out_size)
{
    const float* x0 = (const float*)d_in[0];   // x0_sample [B]
    const float* sw = (const float*)d_in[1];   // sin_weight [8]
    const float* cw = (const float*)d_in[2];   // cos_weight [8]
    // d_in[3] (t_sample) does not affect the output.
    const int B = in_sizes[0];
    const int blocks = (B + EPB - 1) / EPB;    // 4096 for B = 1048576
    drifter_kernel<<<blocks, TPB>>>(x0, sw, cw, (float*)d_out, B);
}